// round 1
// baseline (speedup 1.0000x reference)
#include <cuda_runtime.h>
#include <math.h>

// Problem constants
#define MROWS 8192          // B*N
#define CDIM  1024
#define HID   4096
#define NHEAD 16
#define DHEAD 64
#define SEQ   1024
#define LN_EPS 1e-5f

// ---------------- scratch (no allocations allowed) ----------------
__device__ float g_lnA[MROWS * CDIM];
__device__ float g_lnB[MROWS * CDIM];
__device__ float g_q  [MROWS * CDIM];
__device__ float g_k  [MROWS * CDIM];
__device__ float g_v  [MROWS * CDIM];
__device__ float g_ao [MROWS * CDIM];
__device__ float g_acc[MROWS * CDIM];
__device__ float g_h  [MROWS * HID];

// ---------------- LayerNorm: one block per row of 1024 ----------------
__global__ void __launch_bounds__(256) ln_kernel(
    const float* __restrict__ x, const float* __restrict__ g,
    const float* __restrict__ b, float* __restrict__ out)
{
    int row = blockIdx.x;
    int t = threadIdx.x;
    const float4* xr = (const float4*)(x + (size_t)row * CDIM);
    float4 v = xr[t];
    float s  = v.x + v.y + v.z + v.w;
    float sq = v.x * v.x + v.y * v.y + v.z * v.z + v.w * v.w;
    #pragma unroll
    for (int o = 16; o > 0; o >>= 1) {
        s  += __shfl_xor_sync(0xffffffffu, s,  o);
        sq += __shfl_xor_sync(0xffffffffu, sq, o);
    }
    __shared__ float ss[8], ssq[8];
    __shared__ float red[2];
    int w = t >> 5, lane = t & 31;
    if (lane == 0) { ss[w] = s; ssq[w] = sq; }
    __syncthreads();
    if (w == 0) {
        float a  = (lane < 8) ? ss[lane]  : 0.f;
        float aq = (lane < 8) ? ssq[lane] : 0.f;
        #pragma unroll
        for (int o = 4; o > 0; o >>= 1) {
            a  += __shfl_xor_sync(0xffffffffu, a,  o);
            aq += __shfl_xor_sync(0xffffffffu, aq, o);
        }
        if (lane == 0) {
            float mean = a * (1.0f / CDIM);
            float var  = aq * (1.0f / CDIM) - mean * mean;
            red[0] = mean;
            red[1] = rsqrtf(var + LN_EPS);
        }
    }
    __syncthreads();
    float mean = red[0], rstd = red[1];
    float4 gg = ((const float4*)g)[t];
    float4 bb = ((const float4*)b)[t];
    float4 o4;
    o4.x = (v.x - mean) * rstd * gg.x + bb.x;
    o4.y = (v.y - mean) * rstd * gg.y + bb.y;
    o4.z = (v.z - mean) * rstd * gg.z + bb.z;
    o4.w = (v.w - mean) * rstd * gg.w + bb.w;
    ((float4*)(out + (size_t)row * CDIM))[t] = o4;
}

// ---------------- SGEMM 128x128x16, 256 threads, 8x8 per thread ----------------
// C = A[M,K] @ B[K,N]  (+bias[col]) (gelu if act==1) (+add[row,col])
__global__ void __launch_bounds__(256) sgemm_kernel(
    const float* __restrict__ A, const float* __restrict__ B, float* __restrict__ Cout,
    int M, int N, int K,
    const float* __restrict__ bias, const float* __restrict__ add, int act)
{
    const int BM = 128, BN = 128, BK = 16;
    __shared__ float As[BK][BM];
    __shared__ float Bs[BK][BN];
    int bm = blockIdx.y, bn = blockIdx.x;
    int tid = threadIdx.x;
    int tx = tid & 15, ty = tid >> 4;

    float acc[8][8];
    #pragma unroll
    for (int i = 0; i < 8; i++)
        #pragma unroll
        for (int j = 0; j < 8; j++) acc[i][j] = 0.f;

    const float* Ablk = A + (size_t)bm * BM * K;
    const float* Bblk = B + (size_t)bn * BN;

    for (int kt = 0; kt < K; kt += BK) {
        // A tile: 128 rows x 16 cols, store transposed As[k][m]
        #pragma unroll
        for (int i = 0; i < 2; i++) {
            int f = tid + i * 256;           // 0..511
            int row = f >> 2, c4 = f & 3;
            float4 a = *(const float4*)(Ablk + (size_t)row * K + kt + c4 * 4);
            As[c4 * 4 + 0][row] = a.x;
            As[c4 * 4 + 1][row] = a.y;
            As[c4 * 4 + 2][row] = a.z;
            As[c4 * 4 + 3][row] = a.w;
        }
        // B tile: 16 rows x 128 cols, direct
        #pragma unroll
        for (int i = 0; i < 2; i++) {
            int f = tid + i * 256;
            int row = f >> 5, c4 = f & 31;
            *(float4*)&Bs[row][c4 * 4] =
                *(const float4*)(Bblk + (size_t)(kt + row) * N + c4 * 4);
        }
        __syncthreads();
        #pragma unroll
        for (int kk = 0; kk < BK; kk++) {
            float a[8], b[8];
            *(float4*)(a)     = *(float4*)&As[kk][ty * 8];
            *(float4*)(a + 4) = *(float4*)&As[kk][ty * 8 + 4];
            *(float4*)(b)     = *(float4*)&Bs[kk][tx * 8];
            *(float4*)(b + 4) = *(float4*)&Bs[kk][tx * 8 + 4];
            #pragma unroll
            for (int i = 0; i < 8; i++)
                #pragma unroll
                for (int j = 0; j < 8; j++)
                    acc[i][j] += a[i] * b[j];
        }
        __syncthreads();
    }

    int row0 = bm * BM + ty * 8;
    int col0 = bn * BN + tx * 8;
    #pragma unroll
    for (int i = 0; i < 8; i++) {
        size_t ro = (size_t)(row0 + i) * N;
        #pragma unroll
        for (int j = 0; j < 8; j++) {
            float vv = acc[i][j];
            int col = col0 + j;
            if (bias) vv += bias[col];
            if (act == 1) vv = 0.5f * vv * (1.0f + erff(vv * 0.70710678118654752f));
            if (add) vv += add[ro + col];
            Cout[ro + col] = vv;
        }
    }
}

// ---------------- Flash attention: Br=Bc=64, d=64, fp32 ----------------
// Q,K,V stored [8192, 1024]; head h lives at cols [h*64, h*64+64).
#define FL_PAD 68
#define FL_SMEM (4 * 64 * FL_PAD * 4)

__global__ void __launch_bounds__(256) flash_kernel(
    const float* __restrict__ Q, const float* __restrict__ Kx,
    const float* __restrict__ V, float* __restrict__ O)
{
    extern __shared__ float sm[];
    float (*Qts)[FL_PAD] = (float (*)[FL_PAD])(sm);                 // [64][68] Q^T: Qts[kk][row]
    float (*Kts)[FL_PAD] = (float (*)[FL_PAD])(sm + 64 * FL_PAD);   // K^T: Kts[kk][col]
    float (*Vs )[FL_PAD] = (float (*)[FL_PAD])(sm + 2 * 64 * FL_PAD); // V: Vs[row][d]
    float (*Ps )[FL_PAD] = (float (*)[FL_PAD])(sm + 3 * 64 * FL_PAD); // P: Ps[row][col]

    int bh = blockIdx.x;                 // 0..127 = b*16+h
    int b = bh / NHEAD, h = bh % NHEAD;
    int qt = blockIdx.y;                 // 0..15
    int tid = threadIdx.x;
    int tx = tid & 15, ty = tid >> 4;
    int r0 = ty * 4, c0 = tx * 4;
    size_t base = ((size_t)b * SEQ) * CDIM + h * DHEAD;

    // Load Q tile transposed: Qts[kk][row]
    #pragma unroll
    for (int i = 0; i < 4; i++) {
        int f = tid + i * 256;           // 0..1023
        int row = f >> 4, c4 = f & 15;
        float4 a = *(const float4*)(Q + base + (size_t)(qt * 64 + row) * CDIM + c4 * 4);
        Qts[c4 * 4 + 0][row] = a.x;
        Qts[c4 * 4 + 1][row] = a.y;
        Qts[c4 * 4 + 2][row] = a.z;
        Qts[c4 * 4 + 3][row] = a.w;
    }

    float m[4], l[4], o[4][4];
    #pragma unroll
    for (int i = 0; i < 4; i++) {
        m[i] = -1e30f; l[i] = 0.f;
        #pragma unroll
        for (int j = 0; j < 4; j++) o[i][j] = 0.f;
    }

    const float scale = 0.125f;  // 1/sqrt(64)

    for (int kt = 0; kt < SEQ / 64; kt++) {
        __syncthreads();
        // Load K transposed + V direct
        #pragma unroll
        for (int i = 0; i < 4; i++) {
            int f = tid + i * 256;
            int row = f >> 4, c4 = f & 15;
            float4 a = *(const float4*)(Kx + base + (size_t)(kt * 64 + row) * CDIM + c4 * 4);
            Kts[c4 * 4 + 0][row] = a.x;
            Kts[c4 * 4 + 1][row] = a.y;
            Kts[c4 * 4 + 2][row] = a.z;
            Kts[c4 * 4 + 3][row] = a.w;
            *(float4*)&Vs[row][c4 * 4] =
                *(const float4*)(V + base + (size_t)(kt * 64 + row) * CDIM + c4 * 4);
        }
        __syncthreads();

        // S = scale * Q K^T  (outer-product over kk)
        float s[4][4];
        #pragma unroll
        for (int i = 0; i < 4; i++)
            #pragma unroll
            for (int j = 0; j < 4; j++) s[i][j] = 0.f;
        #pragma unroll 8
        for (int kk = 0; kk < DHEAD; kk++) {
            float4 q4 = *(float4*)&Qts[kk][r0];
            float4 k4 = *(float4*)&Kts[kk][c0];
            float qa[4] = {q4.x, q4.y, q4.z, q4.w};
            float ka[4] = {k4.x, k4.y, k4.z, k4.w};
            #pragma unroll
            for (int i = 0; i < 4; i++)
                #pragma unroll
                for (int j = 0; j < 4; j++)
                    s[i][j] += qa[i] * ka[j];
        }

        // Online softmax (row reductions across the 16 tx lanes, width-16 shuffles)
        #pragma unroll
        for (int i = 0; i < 4; i++) {
            float tmax = -1e30f;
            #pragma unroll
            for (int j = 0; j < 4; j++) {
                s[i][j] *= scale;
                tmax = fmaxf(tmax, s[i][j]);
            }
            #pragma unroll
            for (int off = 8; off > 0; off >>= 1)
                tmax = fmaxf(tmax, __shfl_xor_sync(0xffffffffu, tmax, off, 16));
            float mn = fmaxf(m[i], tmax);
            float al = __expf(m[i] - mn);
            float rs = 0.f;
            #pragma unroll
            for (int j = 0; j < 4; j++) {
                s[i][j] = __expf(s[i][j] - mn);
                rs += s[i][j];
            }
            #pragma unroll
            for (int off = 8; off > 0; off >>= 1)
                rs += __shfl_xor_sync(0xffffffffu, rs, off, 16);
            l[i] = l[i] * al + rs;
            m[i] = mn;
            #pragma unroll
            for (int j = 0; j < 4; j++) o[i][j] *= al;
            *(float4*)&Ps[r0 + i][c0] = make_float4(s[i][0], s[i][1], s[i][2], s[i][3]);
        }
        __syncthreads();

        // O += P @ V
        #pragma unroll 8
        for (int c = 0; c < 64; c++) {
            float4 v4 = *(float4*)&Vs[c][c0];
            #pragma unroll
            for (int i = 0; i < 4; i++) {
                float p = Ps[r0 + i][c];
                o[i][0] += p * v4.x;
                o[i][1] += p * v4.y;
                o[i][2] += p * v4.z;
                o[i][3] += p * v4.w;
            }
        }
    }

    // Write normalized output
    #pragma unroll
    for (int i = 0; i < 4; i++) {
        float inv = 1.0f / l[i];
        float4 r = make_float4(o[i][0] * inv, o[i][1] * inv, o[i][2] * inv, o[i][3] * inv);
        *(float4*)(O + base + (size_t)(qt * 64 + r0 + i) * CDIM + c0) = r;
    }
}

// ---------------- launch ----------------
extern "C" void kernel_launch(void* const* d_in, const int* in_sizes, int n_in,
                              void* d_out, int out_size)
{
    const float* x1     = (const float*)d_in[0];
    const float* x2     = (const float*)d_in[1];
    const float* x3     = (const float*)d_in[2];
    const float* ln11_g = (const float*)d_in[3];
    const float* ln11_b = (const float*)d_in[4];
    const float* ln12_g = (const float*)d_in[5];
    const float* ln12_b = (const float*)d_in[6];
    const float* ln21_g = (const float*)d_in[7];
    const float* ln21_b = (const float*)d_in[8];
    const float* ln23_g = (const float*)d_in[9];
    const float* ln23_b = (const float*)d_in[10];
    const float* ln2_g  = (const float*)d_in[11];
    const float* ln2_b  = (const float*)d_in[12];
    const float* a1_wq  = (const float*)d_in[13];
    const float* a1_wk  = (const float*)d_in[14];
    const float* a1_wv  = (const float*)d_in[15];
    const float* a1_wp  = (const float*)d_in[16];
    const float* a1_bp  = (const float*)d_in[17];
    const float* a2_wq  = (const float*)d_in[18];
    const float* a2_wk  = (const float*)d_in[19];
    const float* a2_wv  = (const float*)d_in[20];
    const float* a2_wp  = (const float*)d_in[21];
    const float* a2_bp  = (const float*)d_in[22];
    const float* fc1_w  = (const float*)d_in[23];
    const float* fc1_b  = (const float*)d_in[24];
    const float* fc2_w  = (const float*)d_in[25];
    const float* fc2_b  = (const float*)d_in[26];
    float* out = (float*)d_out;

    float *lnA, *lnB, *q, *k, *v, *ao, *acc, *hbuf;
    cudaGetSymbolAddress((void**)&lnA,  g_lnA);
    cudaGetSymbolAddress((void**)&lnB,  g_lnB);
    cudaGetSymbolAddress((void**)&q,    g_q);
    cudaGetSymbolAddress((void**)&k,    g_k);
    cudaGetSymbolAddress((void**)&v,    g_v);
    cudaGetSymbolAddress((void**)&ao,   g_ao);
    cudaGetSymbolAddress((void**)&acc,  g_acc);
    cudaGetSymbolAddress((void**)&hbuf, g_h);

    cudaFuncSetAttribute(flash_kernel, cudaFuncAttributeMaxDynamicSharedMemorySize, FL_SMEM);

    dim3 gLN(MROWS);
    dim3 g1k(CDIM / 128, MROWS / 128);     // N=1024 GEMMs
    dim3 gH (HID  / 128, MROWS / 128);     // N=4096 GEMM
    dim3 gFl(128, 16);

    // ---- branch 1: cross_attn(ln11(x1), ln12(x2)) ----
    ln_kernel<<<gLN, 256>>>(x1, ln11_g, ln11_b, lnA);
    ln_kernel<<<gLN, 256>>>(x2, ln12_g, ln12_b, lnB);
    sgemm_kernel<<<g1k, 256>>>(lnA, a1_wq, q, MROWS, CDIM, CDIM, nullptr, nullptr, 0);
    sgemm_kernel<<<g1k, 256>>>(lnB, a1_wk, k, MROWS, CDIM, CDIM, nullptr, nullptr, 0);
    sgemm_kernel<<<g1k, 256>>>(lnB, a1_wv, v, MROWS, CDIM, CDIM, nullptr, nullptr, 0);
    flash_kernel<<<gFl, 256, FL_SMEM>>>(q, k, v, ao);
    // acc = x1 + br1
    sgemm_kernel<<<g1k, 256>>>(ao, a1_wp, acc, MROWS, CDIM, CDIM, a1_bp, x1, 0);

    // ---- branch 2: cross_attn(ln21(x1), ln23(x3)) ----
    ln_kernel<<<gLN, 256>>>(x1, ln21_g, ln21_b, lnA);
    ln_kernel<<<gLN, 256>>>(x3, ln23_g, ln23_b, lnB);
    sgemm_kernel<<<g1k, 256>>>(lnA, a2_wq, q, MROWS, CDIM, CDIM, nullptr, nullptr, 0);
    sgemm_kernel<<<g1k, 256>>>(lnB, a2_wk, k, MROWS, CDIM, CDIM, nullptr, nullptr, 0);
    sgemm_kernel<<<g1k, 256>>>(lnB, a2_wv, v, MROWS, CDIM, CDIM, nullptr, nullptr, 0);
    flash_kernel<<<gFl, 256, FL_SMEM>>>(q, k, v, ao);
    // acc = acc + br2
    sgemm_kernel<<<g1k, 256>>>(ao, a2_wp, acc, MROWS, CDIM, CDIM, a2_bp, acc, 0);

    // ---- MLP ----
    ln_kernel<<<gLN, 256>>>(acc, ln2_g, ln2_b, lnA);
    sgemm_kernel<<<gH, 256>>>(lnA, fc1_w, hbuf, MROWS, HID, CDIM, fc1_b, nullptr, 1);
    sgemm_kernel<<<g1k, 256>>>(hbuf, fc2_w, out, MROWS, CDIM, HID, fc2_b, acc, 0);
}

// round 5
// speedup vs baseline: 1.8135x; 1.8135x over previous
#include <cuda_runtime.h>
#include <math.h>
#include <stdint.h>

// Problem constants
#define MROWS 8192          // B*N
#define CDIM  1024
#define HID   4096
#define NHEAD 16
#define DHEAD 64
#define SEQ   1024
#define LN_EPS 1e-5f

// ---------------- scratch (no allocations allowed) ----------------
__device__ float g_lnA[MROWS * CDIM];
__device__ float g_lnB[MROWS * CDIM];
__device__ float g_q  [MROWS * CDIM];
__device__ float g_k  [MROWS * CDIM];
__device__ float g_v  [MROWS * CDIM];
__device__ float g_ao [MROWS * CDIM];
__device__ float g_acc[MROWS * CDIM];
__device__ float g_h  [MROWS * HID];

// ---------------- LayerNorm: one block per row of 1024 ----------------
__global__ void __launch_bounds__(256) ln_kernel(
    const float* __restrict__ x, const float* __restrict__ g,
    const float* __restrict__ b, float* __restrict__ out)
{
    int row = blockIdx.x;
    int t = threadIdx.x;
    const float4* xr = (const float4*)(x + (size_t)row * CDIM);
    float4 v = xr[t];
    float s  = v.x + v.y + v.z + v.w;
    float sq = v.x * v.x + v.y * v.y + v.z * v.z + v.w * v.w;
    #pragma unroll
    for (int o = 16; o > 0; o >>= 1) {
        s  += __shfl_xor_sync(0xffffffffu, s,  o);
        sq += __shfl_xor_sync(0xffffffffu, sq, o);
    }
    __shared__ float ss[8], ssq[8];
    __shared__ float red[2];
    int w = t >> 5, lane = t & 31;
    if (lane == 0) { ss[w] = s; ssq[w] = sq; }
    __syncthreads();
    if (w == 0) {
        float a  = (lane < 8) ? ss[lane]  : 0.f;
        float aq = (lane < 8) ? ssq[lane] : 0.f;
        #pragma unroll
        for (int o = 4; o > 0; o >>= 1) {
            a  += __shfl_xor_sync(0xffffffffu, a,  o);
            aq += __shfl_xor_sync(0xffffffffu, aq, o);
        }
        if (lane == 0) {
            float mean = a * (1.0f / CDIM);
            float var  = aq * (1.0f / CDIM) - mean * mean;
            red[0] = mean;
            red[1] = rsqrtf(var + LN_EPS);
        }
    }
    __syncthreads();
    float mean = red[0], rstd = red[1];
    float4 gg = ((const float4*)g)[t];
    float4 bb = ((const float4*)b)[t];
    float4 o4;
    o4.x = (v.x - mean) * rstd * gg.x + bb.x;
    o4.y = (v.y - mean) * rstd * gg.y + bb.y;
    o4.z = (v.z - mean) * rstd * gg.z + bb.z;
    o4.w = (v.w - mean) * rstd * gg.w + bb.w;
    ((float4*)(out + (size_t)row * CDIM))[t] = o4;
}

// ---------------- TF32 tensor-core GEMM 128x128x32 ----------------
// C = A[M,K] @ B[K,N]  (+bias[col]) (gelu if act==1) (+add[row,col])
// SMEM fragment-packed layout: element (row, col) of a 128x32 tile stored at
//   smem[row*48 + (((col&7) ^ (row&7)) * 4) + (col>>3)]
// so each mma fragment register group (4 consecutive k-steps) is one LDS.128,
// conflict-free (stride 48 floats + XOR swizzle).

#define GS 48
#define TILE_F (128 * GS)          // floats per tile
#define BUF_F  (2 * TILE_F)        // A tile + B tile per buffer
#define GEMM_SMEM (2 * BUF_F * 4)  // bytes, double buffered = 98304

__device__ __forceinline__ float to_tf32(float x) {
    unsigned u;
    asm("cvt.rna.tf32.f32 %0, %1;" : "=r"(u) : "f"(x));
    return __uint_as_float(u);
}

__device__ __forceinline__ void mma_tf32(float4& d,
    unsigned a0, unsigned a1, unsigned a2, unsigned a3,
    unsigned b0, unsigned b1)
{
    asm volatile(
        "mma.sync.aligned.m16n8k8.row.col.f32.tf32.tf32.f32 "
        "{%0,%1,%2,%3}, {%4,%5,%6,%7}, {%8,%9}, {%0,%1,%2,%3};\n"
        : "+f"(d.x), "+f"(d.y), "+f"(d.z), "+f"(d.w)
        : "r"(a0), "r"(a1), "r"(a2), "r"(a3), "r"(b0), "r"(b1));
}

__global__ void __launch_bounds__(256, 1) tf32_gemm_kernel(
    const float* __restrict__ A, const float* __restrict__ B, float* __restrict__ Cout,
    int M, int N, int K,
    const float* __restrict__ bias, const float* __restrict__ add, int act)
{
    extern __shared__ float sm[];
    int tid = threadIdx.x;
    int lane = tid & 31, warp = tid >> 5;
    int wm = warp & 3, wn = warp >> 1 & 0 ? 0 : (warp >> 2);   // wm 0..3, wn 0..1
    int g = lane >> 2, t = lane & 3;
    int bm = blockIdx.y, bn = blockIdx.x;

    float4 acc[2][8];
    #pragma unroll
    for (int i = 0; i < 2; i++)
        #pragma unroll
        for (int j = 0; j < 8; j++) acc[i][j] = make_float4(0.f, 0.f, 0.f, 0.f);

    // global load assignments
    int arow = tid >> 3;              // 0..31 (+32*i)
    int ac4  = tid & 7;               // float4 index within 32-col slab
    const float* Aptr = A + (size_t)(bm * 128 + arow) * K + ac4 * 4;
    int bk  = tid >> 3;               // 0..31 k within tile
    int bn4 = tid & 7;                // float4 index within 32 n (+32*i)
    const float* Bptr = B + (size_t)bk * N + bn * 128 + bn4 * 4;

    // swizzled store slot helpers (precomputed parts)
    // A element (row, col): slot = (((col&7)^(row&7))*4) + (col>>3)
    // thread's A cols: col = ac4*4 + e => col&7 = (ac4&1)*4 + e, col>>3 = ac4>>1
    int a_c7base = (ac4 & 1) * 4;
    int a_ks = ac4 >> 1;

    float4 pa[4], pb[4];
    #pragma unroll
    for (int i = 0; i < 4; i++) {
        pa[i] = *(const float4*)(Aptr + (size_t)(32 * i) * K);
        pb[i] = *(const float4*)(Bptr + 32 * i);
    }
    // store prologue tile into buffer 0
    {
        float* As = sm;
        float* Bs = sm + TILE_F;
        #pragma unroll
        for (int i = 0; i < 4; i++) {
            int row = arow + 32 * i;
            float* dst = As + row * GS;
            float e0 = to_tf32(pa[i].x), e1 = to_tf32(pa[i].y);
            float e2 = to_tf32(pa[i].z), e3 = to_tf32(pa[i].w);
            int r7 = row & 7;
            dst[(((a_c7base + 0) ^ r7) * 4) + a_ks] = e0;
            dst[(((a_c7base + 1) ^ r7) * 4) + a_ks] = e1;
            dst[(((a_c7base + 2) ^ r7) * 4) + a_ks] = e2;
            dst[(((a_c7base + 3) ^ r7) * 4) + a_ks] = e3;
        }
        int k7 = bk & 7, kks = bk >> 3;
        #pragma unroll
        for (int i = 0; i < 4; i++) {
            int n0 = bn4 * 4 + 32 * i;
            float e[4] = { to_tf32(pb[i].x), to_tf32(pb[i].y),
                           to_tf32(pb[i].z), to_tf32(pb[i].w) };
            #pragma unroll
            for (int ee = 0; ee < 4; ee++) {
                int n = n0 + ee;
                Bs[n * GS + ((k7 ^ (n & 7)) * 4) + kks] = e[ee];
            }
        }
    }
    __syncthreads();

    int nk = K >> 5;
    for (int kt = 0; kt < nk; kt++) {
        const float* As = sm + (kt & 1) * BUF_F;
        const float* Bs = As + TILE_F;

        if (kt + 1 < nk) {
            const float* Ap = Aptr + (kt + 1) * 32;
            const float* Bp = Bptr + (size_t)(kt + 1) * 32 * N;
            #pragma unroll
            for (int i = 0; i < 4; i++) {
                pa[i] = *(const float4*)(Ap + (size_t)(32 * i) * K);
                pb[i] = *(const float4*)(Bp + 32 * i);
            }
        }

        // load all A fragments (8 LDS.128)
        float4 af[2][4];
        #pragma unroll
        for (int i = 0; i < 2; i++) {
            int r  = wm * 32 + i * 16 + g;
            int r8 = r + 8;
            af[i][0] = *(const float4*)&As[r  * GS + ((t       ^ (r  & 7)) * 4)];
            af[i][1] = *(const float4*)&As[r8 * GS + ((t       ^ (r8 & 7)) * 4)];
            af[i][2] = *(const float4*)&As[r  * GS + (((t + 4) ^ (r  & 7)) * 4)];
            af[i][3] = *(const float4*)&As[r8 * GS + (((t + 4) ^ (r8 & 7)) * 4)];
        }

        #pragma unroll
        for (int j = 0; j < 8; j++) {
            int n = wn * 64 + j * 8 + g;
            float4 b0 = *(const float4*)&Bs[n * GS + ((t       ^ (n & 7)) * 4)];
            float4 b1 = *(const float4*)&Bs[n * GS + (((t + 4) ^ (n & 7)) * 4)];
            const unsigned* b0u = (const unsigned*)&b0;
            const unsigned* b1u = (const unsigned*)&b1;
            #pragma unroll
            for (int ks = 0; ks < 4; ks++) {
                #pragma unroll
                for (int i = 0; i < 2; i++) {
                    const unsigned* a0u = (const unsigned*)&af[i][0];
                    const unsigned* a1u = (const unsigned*)&af[i][1];
                    const unsigned* a2u = (const unsigned*)&af[i][2];
                    const unsigned* a3u = (const unsigned*)&af[i][3];
                    mma_tf32(acc[i][j], a0u[ks], a1u[ks], a2u[ks], a3u[ks],
                             b0u[ks], b1u[ks]);
                }
            }
        }

        if (kt + 1 < nk) {
            float* Asn = sm + ((kt + 1) & 1) * BUF_F;
            float* Bsn = Asn + TILE_F;
            #pragma unroll
            for (int i = 0; i < 4; i++) {
                int row = arow + 32 * i;
                float* dst = Asn + row * GS;
                float e0 = to_tf32(pa[i].x), e1 = to_tf32(pa[i].y);
                float e2 = to_tf32(pa[i].z), e3 = to_tf32(pa[i].w);
                int r7 = row & 7;
                dst[(((a_c7base + 0) ^ r7) * 4) + a_ks] = e0;
                dst[(((a_c7base + 1) ^ r7) * 4) + a_ks] = e1;
                dst[(((a_c7base + 2) ^ r7) * 4) + a_ks] = e2;
                dst[(((a_c7base + 3) ^ r7) * 4) + a_ks] = e3;
            }
            int k7 = bk & 7, kks = bk >> 3;
            #pragma unroll
            for (int i = 0; i < 4; i++) {
                int n0 = bn4 * 4 + 32 * i;
                float e[4] = { to_tf32(pb[i].x), to_tf32(pb[i].y),
                               to_tf32(pb[i].z), to_tf32(pb[i].w) };
                #pragma unroll
                for (int ee = 0; ee < 4; ee++) {
                    int n = n0 + ee;
                    Bsn[n * GS + ((k7 ^ (n & 7)) * 4) + kks] = e[ee];
                }
            }
        }
        __syncthreads();
    }

    // epilogue
    int rbase = bm * 128 + wm * 32;
    int cbase = bn * 128 + wn * 64;
    #pragma unroll
    for (int i = 0; i < 2; i++) {
        int r0 = rbase + i * 16 + g;
        int r1 = r0 + 8;
        #pragma unroll
        for (int j = 0; j < 8; j++) {
            int c = cbase + j * 8 + t * 2;
            float v0 = acc[i][j].x, v1 = acc[i][j].y;
            float v2 = acc[i][j].z, v3 = acc[i][j].w;
            if (bias) {
                float b0 = bias[c], b1 = bias[c + 1];
                v0 += b0; v1 += b1; v2 += b0; v3 += b1;
            }
            if (act == 1) {
                v0 = 0.5f * v0 * (1.0f + erff(v0 * 0.70710678118654752f));
                v1 = 0.5f * v1 * (1.0f + erff(v1 * 0.70710678118654752f));
                v2 = 0.5f * v2 * (1.0f + erff(v2 * 0.70710678118654752f));
                v3 = 0.5f * v3 * (1.0f + erff(v3 * 0.70710678118654752f));
            }
            size_t o0 = (size_t)r0 * N + c;
            size_t o1 = (size_t)r1 * N + c;
            if (add) {
                v0 += add[o0]; v1 += add[o0 + 1];
                v2 += add[o1]; v3 += add[o1 + 1];
            }
            *(float2*)(Cout + o0) = make_float2(v0, v1);
            *(float2*)(Cout + o1) = make_float2(v2, v3);
        }
    }
}

// ---------------- Flash attention: Br=Bc=64, d=64, fp32 ----------------
#define FL_PAD 68
#define FL_SMEM (4 * 64 * FL_PAD * 4)

__global__ void __launch_bounds__(256) flash_kernel(
    const float* __restrict__ Q, const float* __restrict__ Kx,
    const float* __restrict__ V, float* __restrict__ O)
{
    extern __shared__ float sm[];
    float (*Qts)[FL_PAD] = (float (*)[FL_PAD])(sm);
    float (*Kts)[FL_PAD] = (float (*)[FL_PAD])(sm + 64 * FL_PAD);
    float (*Vs )[FL_PAD] = (float (*)[FL_PAD])(sm + 2 * 64 * FL_PAD);
    float (*Ps )[FL_PAD] = (float (*)[FL_PAD])(sm + 3 * 64 * FL_PAD);

    int bh = blockIdx.x;
    int b = bh / NHEAD, h = bh % NHEAD;
    int qt = blockIdx.y;
    int tid = threadIdx.x;
    int tx = tid & 15, ty = tid >> 4;
    int r0 = ty * 4, c0 = tx * 4;
    size_t base = ((size_t)b * SEQ) * CDIM + h * DHEAD;

    #pragma unroll
    for (int i = 0; i < 4; i++) {
        int f = tid + i * 256;
        int row = f >> 4, c4 = f & 15;
        float4 a = *(const float4*)(Q + base + (size_t)(qt * 64 + row) * CDIM + c4 * 4);
        Qts[c4 * 4 + 0][row] = a.x;
        Qts[c4 * 4 + 1][row] = a.y;
        Qts[c4 * 4 + 2][row] = a.z;
        Qts[c4 * 4 + 3][row] = a.w;
    }

    float m[4], l[4], o[4][4];
    #pragma unroll
    for (int i = 0; i < 4; i++) {
        m[i] = -1e30f; l[i] = 0.f;
        #pragma unroll
        for (int j = 0; j < 4; j++) o[i][j] = 0.f;
    }

    const float scale = 0.125f;

    for (int kt = 0; kt < SEQ / 64; kt++) {
        __syncthreads();
        #pragma unroll
        for (int i = 0; i < 4; i++) {
            int f = tid + i * 256;
            int row = f >> 4, c4 = f & 15;
            float4 a = *(const float4*)(Kx + base + (size_t)(kt * 64 + row) * CDIM + c4 * 4);
            Kts[c4 * 4 + 0][row] = a.x;
            Kts[c4 * 4 + 1][row] = a.y;
            Kts[c4 * 4 + 2][row] = a.z;
            Kts[c4 * 4 + 3][row] = a.w;
            *(float4*)&Vs[row][c4 * 4] =
                *(const float4*)(V + base + (size_t)(kt * 64 + row) * CDIM + c4 * 4);
        }
        __syncthreads();

        float s[4][4];
        #pragma unroll
        for (int i = 0; i < 4; i++)
            #pragma unroll
            for (int j = 0; j < 4; j++) s[i][j] = 0.f;
        #pragma unroll 8
        for (int kk = 0; kk < DHEAD; kk++) {
            float4 q4 = *(float4*)&Qts[kk][r0];
            float4 k4 = *(float4*)&Kts[kk][c0];
            float qa[4] = {q4.x, q4.y, q4.z, q4.w};
            float ka[4] = {k4.x, k4.y, k4.z, k4.w};
            #pragma unroll
            for (int i = 0; i < 4; i++)
                #pragma unroll
                for (int j = 0; j < 4; j++)
                    s[i][j] += qa[i] * ka[j];
        }

        #pragma unroll
        for (int i = 0; i < 4; i++) {
            float tmax = -1e30f;
            #pragma unroll
            for (int j = 0; j < 4; j++) {
                s[i][j] *= scale;
                tmax = fmaxf(tmax, s[i][j]);
            }
            #pragma unroll
            for (int off = 8; off > 0; off >>= 1)
                tmax = fmaxf(tmax, __shfl_xor_sync(0xffffffffu, tmax, off, 16));
            float mn = fmaxf(m[i], tmax);
            float al = __expf(m[i] - mn);
            float rs = 0.f;
            #pragma unroll
            for (int j = 0; j < 4; j++) {
                s[i][j] = __expf(s[i][j] - mn);
                rs += s[i][j];
            }
            #pragma unroll
            for (int off = 8; off > 0; off >>= 1)
                rs += __shfl_xor_sync(0xffffffffu, rs, off, 16);
            l[i] = l[i] * al + rs;
            m[i] = mn;
            #pragma unroll
            for (int j = 0; j < 4; j++) o[i][j] *= al;
            *(float4*)&Ps[r0 + i][c0] = make_float4(s[i][0], s[i][1], s[i][2], s[i][3]);
        }
        __syncthreads();

        #pragma unroll 8
        for (int c = 0; c < 64; c++) {
            float4 v4 = *(float4*)&Vs[c][c0];
            #pragma unroll
            for (int i = 0; i < 4; i++) {
                float p = Ps[r0 + i][c];
                o[i][0] += p * v4.x;
                o[i][1] += p * v4.y;
                o[i][2] += p * v4.z;
                o[i][3] += p * v4.w;
            }
        }
    }

    #pragma unroll
    for (int i = 0; i < 4; i++) {
        float inv = 1.0f / l[i];
        float4 r = make_float4(o[i][0] * inv, o[i][1] * inv, o[i][2] * inv, o[i][3] * inv);
        *(float4*)(O + base + (size_t)(qt * 64 + r0 + i) * CDIM + c0) = r;
    }
}

// ---------------- launch ----------------
extern "C" void kernel_launch(void* const* d_in, const int* in_sizes, int n_in,
                              void* d_out, int out_size)
{
    const float* x1     = (const float*)d_in[0];
    const float* x2     = (const float*)d_in[1];
    const float* x3     = (const float*)d_in[2];
    const float* ln11_g = (const float*)d_in[3];
    const float* ln11_b = (const float*)d_in[4];
    const float* ln12_g = (const float*)d_in[5];
    const float* ln12_b = (const float*)d_in[6];
    const float* ln21_g = (const float*)d_in[7];
    const float* ln21_b = (const float*)d_in[8];
    const float* ln23_g = (const float*)d_in[9];
    const float* ln23_b = (const float*)d_in[10];
    const float* ln2_g  = (const float*)d_in[11];
    const float* ln2_b  = (const float*)d_in[12];
    const float* a1_wq  = (const float*)d_in[13];
    const float* a1_wk  = (const float*)d_in[14];
    const float* a1_wv  = (const float*)d_in[15];
    const float* a1_wp  = (const float*)d_in[16];
    const float* a1_bp  = (const float*)d_in[17];
    const float* a2_wq  = (const float*)d_in[18];
    const float* a2_wk  = (const float*)d_in[19];
    const float* a2_wv  = (const float*)d_in[20];
    const float* a2_wp  = (const float*)d_in[21];
    const float* a2_bp  = (const float*)d_in[22];
    const float* fc1_w  = (const float*)d_in[23];
    const float* fc1_b  = (const float*)d_in[24];
    const float* fc2_w  = (const float*)d_in[25];
    const float* fc2_b  = (const float*)d_in[26];
    float* out = (float*)d_out;

    float *lnA, *lnB, *q, *k, *v, *ao, *acc, *hbuf;
    cudaGetSymbolAddress((void**)&lnA,  g_lnA);
    cudaGetSymbolAddress((void**)&lnB,  g_lnB);
    cudaGetSymbolAddress((void**)&q,    g_q);
    cudaGetSymbolAddress((void**)&k,    g_k);
    cudaGetSymbolAddress((void**)&v,    g_v);
    cudaGetSymbolAddress((void**)&ao,   g_ao);
    cudaGetSymbolAddress((void**)&acc,  g_acc);
    cudaGetSymbolAddress((void**)&hbuf, g_h);

    cudaFuncSetAttribute(flash_kernel, cudaFuncAttributeMaxDynamicSharedMemorySize, FL_SMEM);
    cudaFuncSetAttribute(tf32_gemm_kernel, cudaFuncAttributeMaxDynamicSharedMemorySize, GEMM_SMEM);

    dim3 gLN(MROWS);
    dim3 g1k(CDIM / 128, MROWS / 128);
    dim3 gH (HID  / 128, MROWS / 128);
    dim3 gFl(128, 16);

    // ---- branch 1 ----
    ln_kernel<<<gLN, 256>>>(x1, ln11_g, ln11_b, lnA);
    ln_kernel<<<gLN, 256>>>(x2, ln12_g, ln12_b, lnB);
    tf32_gemm_kernel<<<g1k, 256, GEMM_SMEM>>>(lnA, a1_wq, q, MROWS, CDIM, CDIM, nullptr, nullptr, 0);
    tf32_gemm_kernel<<<g1k, 256, GEMM_SMEM>>>(lnB, a1_wk, k, MROWS, CDIM, CDIM, nullptr, nullptr, 0);
    tf32_gemm_kernel<<<g1k, 256, GEMM_SMEM>>>(lnB, a1_wv, v, MROWS, CDIM, CDIM, nullptr, nullptr, 0);
    flash_kernel<<<gFl, 256, FL_SMEM>>>(q, k, v, ao);
    tf32_gemm_kernel<<<g1k, 256, GEMM_SMEM>>>(ao, a1_wp, acc, MROWS, CDIM, CDIM, a1_bp, x1, 0);

    // ---- branch 2 ----
    ln_kernel<<<gLN, 256>>>(x1, ln21_g, ln21_b, lnA);
    ln_kernel<<<gLN, 256>>>(x3, ln23_g, ln23_b, lnB);
    tf32_gemm_kernel<<<g1k, 256, GEMM_SMEM>>>(lnA, a2_wq, q, MROWS, CDIM, CDIM, nullptr, nullptr, 0);
    tf32_gemm_kernel<<<g1k, 256, GEMM_SMEM>>>(lnB, a2_wk, k, MROWS, CDIM, CDIM, nullptr, nullptr, 0);
    tf32_gemm_kernel<<<g1k, 256, GEMM_SMEM>>>(lnB, a2_wv, v, MROWS, CDIM, CDIM, nullptr, nullptr, 0);
    flash_kernel<<<gFl, 256, FL_SMEM>>>(q, k, v, ao);
    tf32_gemm_kernel<<<g1k, 256, GEMM_SMEM>>>(ao, a2_wp, acc, MROWS, CDIM, CDIM, a2_bp, acc, 0);

    // ---- MLP ----
    ln_kernel<<<gLN, 256>>>(acc, ln2_g, ln2_b, lnA);
    tf32_gemm_kernel<<<gH, 256, GEMM_SMEM>>>(lnA, fc1_w, hbuf, MROWS, HID, CDIM, fc1_b, nullptr, 1);
    tf32_gemm_kernel<<<g1k, 256, GEMM_SMEM>>>(hbuf, fc2_w, out, MROWS, CDIM, HID, fc2_b, acc, 0);
}

// round 7
// speedup vs baseline: 1.8886x; 1.0414x over previous
#include <cuda_runtime.h>
#include <math.h>
#include <stdint.h>

// Problem constants
#define MROWS 8192          // B*N
#define CDIM  1024
#define HID   4096
#define NHEAD 16
#define DHEAD 64
#define SEQ   1024
#define LN_EPS 1e-5f

// ---------------- scratch (no allocations allowed) ----------------
__device__ float g_lnA[MROWS * CDIM];
__device__ float g_lnB[MROWS * CDIM];
__device__ float g_q  [MROWS * CDIM];
__device__ float g_k  [MROWS * CDIM];
__device__ float g_v  [MROWS * CDIM];
__device__ float g_ao [MROWS * CDIM];
__device__ float g_acc[MROWS * CDIM];
__device__ float g_h  [MROWS * HID];

// ---------------- LayerNorm: one block per row of 1024 ----------------
__global__ void __launch_bounds__(256) ln_kernel(
    const float* __restrict__ x, const float* __restrict__ g,
    const float* __restrict__ b, float* __restrict__ out)
{
    int row = blockIdx.x;
    int t = threadIdx.x;
    const float4* xr = (const float4*)(x + (size_t)row * CDIM);
    float4 v = xr[t];
    float s  = v.x + v.y + v.z + v.w;
    float sq = v.x * v.x + v.y * v.y + v.z * v.z + v.w * v.w;
    #pragma unroll
    for (int o = 16; o > 0; o >>= 1) {
        s  += __shfl_xor_sync(0xffffffffu, s,  o);
        sq += __shfl_xor_sync(0xffffffffu, sq, o);
    }
    __shared__ float ss[8], ssq[8];
    __shared__ float red[2];
    int w = t >> 5, lane = t & 31;
    if (lane == 0) { ss[w] = s; ssq[w] = sq; }
    __syncthreads();
    if (w == 0) {
        float a  = (lane < 8) ? ss[lane]  : 0.f;
        float aq = (lane < 8) ? ssq[lane] : 0.f;
        #pragma unroll
        for (int o = 4; o > 0; o >>= 1) {
            a  += __shfl_xor_sync(0xffffffffu, a,  o);
            aq += __shfl_xor_sync(0xffffffffu, aq, o);
        }
        if (lane == 0) {
            float mean = a * (1.0f / CDIM);
            float var  = aq * (1.0f / CDIM) - mean * mean;
            red[0] = mean;
            red[1] = rsqrtf(var + LN_EPS);
        }
    }
    __syncthreads();
    float mean = red[0], rstd = red[1];
    float4 gg = ((const float4*)g)[t];
    float4 bb = ((const float4*)b)[t];
    float4 o4;
    o4.x = (v.x - mean) * rstd * gg.x + bb.x;
    o4.y = (v.y - mean) * rstd * gg.y + bb.y;
    o4.z = (v.z - mean) * rstd * gg.z + bb.z;
    o4.w = (v.w - mean) * rstd * gg.w + bb.w;
    ((float4*)(out + (size_t)row * CDIM))[t] = o4;
}

// ---------------- TF32 tensor-core GEMM 128x128x32 ----------------
// C = A[M,K] @ B[K,N]  (+bias[col]) (gelu if act==1) (+add[row,col])
// SMEM fragment-packed layout (unchanged from passing version):
//   element (row, col) of a 128x32 tile at smem[row*48 + (((col&7)^(row&7))*4) + (col>>3)]
// All addresses are hoisted out of the k-loop:
//   (c0+e)^r7 == (c0 ^ (r7&4)) + (e ^ (r7&3))   (disjoint bit fields)
//   (row+32i)&7 == row&7  => 32i / 8j / 16i row offsets are pure immediates.
// Operands are fed to mma.tf32 as RAW fp32 (HW reads top 19 bits -> truncation).

#define GS 48
#define TILE_F (128 * GS)          // 6144 floats per tile
#define BUF_F  (2 * TILE_F)        // 12288 floats per buffer (A + B)
#define GEMM_SMEM (2 * BUF_F * 4)  // 98304 bytes, double buffered

__device__ __forceinline__ void mma_tf32(float4& d,
    unsigned a0, unsigned a1, unsigned a2, unsigned a3,
    unsigned b0, unsigned b1)
{
    asm volatile(
        "mma.sync.aligned.m16n8k8.row.col.f32.tf32.tf32.f32 "
        "{%0,%1,%2,%3}, {%4,%5,%6,%7}, {%8,%9}, {%0,%1,%2,%3};\n"
        : "+f"(d.x), "+f"(d.y), "+f"(d.z), "+f"(d.w)
        : "r"(a0), "r"(a1), "r"(a2), "r"(a3), "r"(b0), "r"(b1));
}

__global__ void __launch_bounds__(256, 1) tf32_gemm_kernel(
    const float* __restrict__ A, const float* __restrict__ B, float* __restrict__ Cout,
    int M, int N, int K,
    const float* __restrict__ bias, const float* __restrict__ add, int act)
{
    extern __shared__ float sm[];
    int tid = threadIdx.x;
    int lane = tid & 31, warp = tid >> 5;
    int wm = warp & 3, wn = warp >> 2;       // wm 0..3, wn 0..1
    int g = lane >> 2, t = lane & 3;
    int bm = blockIdx.y, bn = blockIdx.x;

    float4 acc[2][8];
    #pragma unroll
    for (int i = 0; i < 2; i++)
        #pragma unroll
        for (int j = 0; j < 8; j++) acc[i][j] = make_float4(0.f, 0.f, 0.f, 0.f);

    // global load assignments
    int arow = tid >> 3;              // A row (0..31, +32i); also B k-row
    int ac4  = tid & 7;               // A float4 col idx; also B n float4 idx
    const float* Aptr = A + (size_t)(bm * 128 + arow) * K + ac4 * 4;
    const float* Bptr = B + (size_t)arow * N + bn * 128 + ac4 * 4;

    // ---- precomputed SMEM store base pointers (buffer 0) ----
    float* sA = sm;                   // A tile buf0
    float* sB = sm + TILE_F;          // B tile buf0
    int r7lo = arow & 3, r7hi = arow & 4;
    int a_c7 = (ac4 & 1) * 4;
    int a_ks = ac4 >> 1;
    float* aSt[4];
    float* bSt[4];
    #pragma unroll
    for (int e = 0; e < 4; e++) {
        aSt[e] = sA + arow * GS + ((a_c7 ^ r7hi) + (e ^ r7lo)) * 4 + a_ks;
        bSt[e] = sB + (ac4 * 4 + e) * GS
                    + ((r7hi ^ ((ac4 & 1) * 4)) + (r7lo ^ e)) * 4 + (arow >> 3);
    }

    // ---- precomputed SMEM load base pointers (buffer 0) ----
    int rA = wm * 32 + g;
    int nB = wn * 64 + g;
    const float* aL0 = sA + rA * GS + ((t    ) ^ g) * 4;
    const float* aL1 = sA + rA * GS + ((t + 4) ^ g) * 4;
    const float* bL0 = sB + nB * GS + ((t    ) ^ g) * 4;
    const float* bL1 = sB + nB * GS + ((t + 4) ^ g) * 4;

    float4 pa[4], pb[4];
    #pragma unroll
    for (int i = 0; i < 4; i++) {
        pa[i] = *(const float4*)(Aptr + (size_t)(32 * i) * K);
        pb[i] = *(const float4*)(Bptr + 32 * i);
    }
    // prologue stores into buffer 0 (immediate offsets: 32 rows = 1536 floats)
    #pragma unroll
    for (int i = 0; i < 4; i++) {
        aSt[0][i * 1536] = pa[i].x;
        aSt[1][i * 1536] = pa[i].y;
        aSt[2][i * 1536] = pa[i].z;
        aSt[3][i * 1536] = pa[i].w;
        bSt[0][i * 1536] = pb[i].x;
        bSt[1][i * 1536] = pb[i].y;
        bSt[2][i * 1536] = pb[i].z;
        bSt[3][i * 1536] = pb[i].w;
    }
    __syncthreads();

    int nk = K >> 5;
    for (int kt = 0; kt < nk; kt++) {
        int boff = (kt & 1) * BUF_F;          // current compute buffer
        int noff = ((kt + 1) & 1) * BUF_F;    // next fill buffer

        if (kt + 1 < nk) {
            const float* Ap = Aptr + (kt + 1) * 32;
            const float* Bp = Bptr + (size_t)(kt + 1) * 32 * N;
            #pragma unroll
            for (int i = 0; i < 4; i++) {
                pa[i] = *(const float4*)(Ap + (size_t)(32 * i) * K);
                pb[i] = *(const float4*)(Bp + 32 * i);
            }
        }

        // A fragments: 8 LDS.128, immediate offsets (16 rows = 768, 8 rows = 384)
        float4 af[2][4];
        #pragma unroll
        for (int i = 0; i < 2; i++) {
            af[i][0] = *(const float4*)(aL0 + boff + i * 768);
            af[i][1] = *(const float4*)(aL0 + boff + i * 768 + 384);
            af[i][2] = *(const float4*)(aL1 + boff + i * 768);
            af[i][3] = *(const float4*)(aL1 + boff + i * 768 + 384);
        }

        #pragma unroll
        for (int j = 0; j < 8; j++) {
            float4 b0 = *(const float4*)(bL0 + boff + j * 384);
            float4 b1 = *(const float4*)(bL1 + boff + j * 384);
            const unsigned* b0u = (const unsigned*)&b0;
            const unsigned* b1u = (const unsigned*)&b1;
            #pragma unroll
            for (int ks = 0; ks < 4; ks++) {
                #pragma unroll
                for (int i = 0; i < 2; i++) {
                    const unsigned* a0u = (const unsigned*)&af[i][0];
                    const unsigned* a1u = (const unsigned*)&af[i][1];
                    const unsigned* a2u = (const unsigned*)&af[i][2];
                    const unsigned* a3u = (const unsigned*)&af[i][3];
                    mma_tf32(acc[i][j], a0u[ks], a1u[ks], a2u[ks], a3u[ks],
                             b0u[ks], b1u[ks]);
                }
            }
        }

        if (kt + 1 < nk) {
            #pragma unroll
            for (int i = 0; i < 4; i++) {
                aSt[0][noff + i * 1536] = pa[i].x;
                aSt[1][noff + i * 1536] = pa[i].y;
                aSt[2][noff + i * 1536] = pa[i].z;
                aSt[3][noff + i * 1536] = pa[i].w;
                bSt[0][noff + i * 1536] = pb[i].x;
                bSt[1][noff + i * 1536] = pb[i].y;
                bSt[2][noff + i * 1536] = pb[i].z;
                bSt[3][noff + i * 1536] = pb[i].w;
            }
        }
        __syncthreads();
    }

    // epilogue
    int rbase = bm * 128 + wm * 32;
    int cbase = bn * 128 + wn * 64;
    #pragma unroll
    for (int i = 0; i < 2; i++) {
        int r0 = rbase + i * 16 + g;
        int r1 = r0 + 8;
        #pragma unroll
        for (int j = 0; j < 8; j++) {
            int c = cbase + j * 8 + t * 2;
            float v0 = acc[i][j].x, v1 = acc[i][j].y;
            float v2 = acc[i][j].z, v3 = acc[i][j].w;
            if (bias) {
                float b0 = bias[c], b1 = bias[c + 1];
                v0 += b0; v1 += b1; v2 += b0; v3 += b1;
            }
            if (act == 1) {
                v0 = 0.5f * v0 * (1.0f + erff(v0 * 0.70710678118654752f));
                v1 = 0.5f * v1 * (1.0f + erff(v1 * 0.70710678118654752f));
                v2 = 0.5f * v2 * (1.0f + erff(v2 * 0.70710678118654752f));
                v3 = 0.5f * v3 * (1.0f + erff(v3 * 0.70710678118654752f));
            }
            size_t o0 = (size_t)r0 * N + c;
            size_t o1 = (size_t)r1 * N + c;
            if (add) {
                v0 += add[o0]; v1 += add[o0 + 1];
                v2 += add[o1]; v3 += add[o1 + 1];
            }
            *(float2*)(Cout + o0) = make_float2(v0, v1);
            *(float2*)(Cout + o1) = make_float2(v2, v3);
        }
    }
}

// ---------------- Flash attention: Br=Bc=64, d=64, fp32 ----------------
#define FL_PAD 68
#define FL_SMEM (4 * 64 * FL_PAD * 4)

__global__ void __launch_bounds__(256) flash_kernel(
    const float* __restrict__ Q, const float* __restrict__ Kx,
    const float* __restrict__ V, float* __restrict__ O)
{
    extern __shared__ float sm[];
    float (*Qts)[FL_PAD] = (float (*)[FL_PAD])(sm);
    float (*Kts)[FL_PAD] = (float (*)[FL_PAD])(sm + 64 * FL_PAD);
    float (*Vs )[FL_PAD] = (float (*)[FL_PAD])(sm + 2 * 64 * FL_PAD);
    float (*Ps )[FL_PAD] = (float (*)[FL_PAD])(sm + 3 * 64 * FL_PAD);

    int bh = blockIdx.x;
    int b = bh / NHEAD, h = bh % NHEAD;
    int qt = blockIdx.y;
    int tid = threadIdx.x;
    int tx = tid & 15, ty = tid >> 4;
    int r0 = ty * 4, c0 = tx * 4;
    size_t base = ((size_t)b * SEQ) * CDIM + h * DHEAD;

    #pragma unroll
    for (int i = 0; i < 4; i++) {
        int f = tid + i * 256;
        int row = f >> 4, c4 = f & 15;
        float4 a = *(const float4*)(Q + base + (size_t)(qt * 64 + row) * CDIM + c4 * 4);
        Qts[c4 * 4 + 0][row] = a.x;
        Qts[c4 * 4 + 1][row] = a.y;
        Qts[c4 * 4 + 2][row] = a.z;
        Qts[c4 * 4 + 3][row] = a.w;
    }

    float m[4], l[4], o[4][4];
    #pragma unroll
    for (int i = 0; i < 4; i++) {
        m[i] = -1e30f; l[i] = 0.f;
        #pragma unroll
        for (int j = 0; j < 4; j++) o[i][j] = 0.f;
    }

    const float scale = 0.125f;

    for (int kt = 0; kt < SEQ / 64; kt++) {
        __syncthreads();
        #pragma unroll
        for (int i = 0; i < 4; i++) {
            int f = tid + i * 256;
            int row = f >> 4, c4 = f & 15;
            float4 a = *(const float4*)(Kx + base + (size_t)(kt * 64 + row) * CDIM + c4 * 4);
            Kts[c4 * 4 + 0][row] = a.x;
            Kts[c4 * 4 + 1][row] = a.y;
            Kts[c4 * 4 + 2][row] = a.z;
            Kts[c4 * 4 + 3][row] = a.w;
            *(float4*)&Vs[row][c4 * 4] =
                *(const float4*)(V + base + (size_t)(kt * 64 + row) * CDIM + c4 * 4);
        }
        __syncthreads();

        float s[4][4];
        #pragma unroll
        for (int i = 0; i < 4; i++)
            #pragma unroll
            for (int j = 0; j < 4; j++) s[i][j] = 0.f;
        #pragma unroll 8
        for (int kk = 0; kk < DHEAD; kk++) {
            float4 q4 = *(float4*)&Qts[kk][r0];
            float4 k4 = *(float4*)&Kts[kk][c0];
            float qa[4] = {q4.x, q4.y, q4.z, q4.w};
            float ka[4] = {k4.x, k4.y, k4.z, k4.w};
            #pragma unroll
            for (int i = 0; i < 4; i++)
                #pragma unroll
                for (int j = 0; j < 4; j++)
                    s[i][j] += qa[i] * ka[j];
        }

        #pragma unroll
        for (int i = 0; i < 4; i++) {
            float tmax = -1e30f;
            #pragma unroll
            for (int j = 0; j < 4; j++) {
                s[i][j] *= scale;
                tmax = fmaxf(tmax, s[i][j]);
            }
            #pragma unroll
            for (int off = 8; off > 0; off >>= 1)
                tmax = fmaxf(tmax, __shfl_xor_sync(0xffffffffu, tmax, off, 16));
            float mn = fmaxf(m[i], tmax);
            float al = __expf(m[i] - mn);
            float rs = 0.f;
            #pragma unroll
            for (int j = 0; j < 4; j++) {
                s[i][j] = __expf(s[i][j] - mn);
                rs += s[i][j];
            }
            #pragma unroll
            for (int off = 8; off > 0; off >>= 1)
                rs += __shfl_xor_sync(0xffffffffu, rs, off, 16);
            l[i] = l[i] * al + rs;
            m[i] = mn;
            #pragma unroll
            for (int j = 0; j < 4; j++) o[i][j] *= al;
            *(float4*)&Ps[r0 + i][c0] = make_float4(s[i][0], s[i][1], s[i][2], s[i][3]);
        }
        __syncthreads();

        // O += P @ V  (vectorized P loads: stride 272B rows are 16B-aligned)
        #pragma unroll 4
        for (int c = 0; c < 64; c += 4) {
            float4 p0 = *(float4*)&Ps[r0 + 0][c];
            float4 p1 = *(float4*)&Ps[r0 + 1][c];
            float4 p2 = *(float4*)&Ps[r0 + 2][c];
            float4 p3 = *(float4*)&Ps[r0 + 3][c];
            const float* pp0 = (const float*)&p0;
            const float* pp1 = (const float*)&p1;
            const float* pp2 = (const float*)&p2;
            const float* pp3 = (const float*)&p3;
            #pragma unroll
            for (int cc = 0; cc < 4; cc++) {
                float4 v4 = *(float4*)&Vs[c + cc][c0];
                float e0 = pp0[cc], e1 = pp1[cc], e2 = pp2[cc], e3 = pp3[cc];
                o[0][0] += e0 * v4.x; o[0][1] += e0 * v4.y;
                o[0][2] += e0 * v4.z; o[0][3] += e0 * v4.w;
                o[1][0] += e1 * v4.x; o[1][1] += e1 * v4.y;
                o[1][2] += e1 * v4.z; o[1][3] += e1 * v4.w;
                o[2][0] += e2 * v4.x; o[2][1] += e2 * v4.y;
                o[2][2] += e2 * v4.z; o[2][3] += e2 * v4.w;
                o[3][0] += e3 * v4.x; o[3][1] += e3 * v4.y;
                o[3][2] += e3 * v4.z; o[3][3] += e3 * v4.w;
            }
        }
    }

    #pragma unroll
    for (int i = 0; i < 4; i++) {
        float inv = 1.0f / l[i];
        float4 r = make_float4(o[i][0] * inv, o[i][1] * inv, o[i][2] * inv, o[i][3] * inv);
        *(float4*)(O + base + (size_t)(qt * 64 + r0 + i) * CDIM + c0) = r;
    }
}

// ---------------- launch ----------------
extern "C" void kernel_launch(void* const* d_in, const int* in_sizes, int n_in,
                              void* d_out, int out_size)
{
    const float* x1     = (const float*)d_in[0];
    const float* x2     = (const float*)d_in[1];
    const float* x3     = (const float*)d_in[2];
    const float* ln11_g = (const float*)d_in[3];
    const float* ln11_b = (const float*)d_in[4];
    const float* ln12_g = (const float*)d_in[5];
    const float* ln12_b = (const float*)d_in[6];
    const float* ln21_g = (const float*)d_in[7];
    const float* ln21_b = (const float*)d_in[8];
    const float* ln23_g = (const float*)d_in[9];
    const float* ln23_b = (const float*)d_in[10];
    const float* ln2_g  = (const float*)d_in[11];
    const float* ln2_b  = (const float*)d_in[12];
    const float* a1_wq  = (const float*)d_in[13];
    const float* a1_wk  = (const float*)d_in[14];
    const float* a1_wv  = (const float*)d_in[15];
    const float* a1_wp  = (const float*)d_in[16];
    const float* a1_bp  = (const float*)d_in[17];
    const float* a2_wq  = (const float*)d_in[18];
    const float* a2_wk  = (const float*)d_in[19];
    const float* a2_wv  = (const float*)d_in[20];
    const float* a2_wp  = (const float*)d_in[21];
    const float* a2_bp  = (const float*)d_in[22];
    const float* fc1_w  = (const float*)d_in[23];
    const float* fc1_b  = (const float*)d_in[24];
    const float* fc2_w  = (const float*)d_in[25];
    const float* fc2_b  = (const float*)d_in[26];
    float* out = (float*)d_out;

    float *lnA, *lnB, *q, *k, *v, *ao, *acc, *hbuf;
    cudaGetSymbolAddress((void**)&lnA,  g_lnA);
    cudaGetSymbolAddress((void**)&lnB,  g_lnB);
    cudaGetSymbolAddress((void**)&q,    g_q);
    cudaGetSymbolAddress((void**)&k,    g_k);
    cudaGetSymbolAddress((void**)&v,    g_v);
    cudaGetSymbolAddress((void**)&ao,   g_ao);
    cudaGetSymbolAddress((void**)&acc,  g_acc);
    cudaGetSymbolAddress((void**)&hbuf, g_h);

    cudaFuncSetAttribute(flash_kernel, cudaFuncAttributeMaxDynamicSharedMemorySize, FL_SMEM);
    cudaFuncSetAttribute(tf32_gemm_kernel, cudaFuncAttributeMaxDynamicSharedMemorySize, GEMM_SMEM);

    dim3 gLN(MROWS);
    dim3 g1k(CDIM / 128, MROWS / 128);
    dim3 gH (HID  / 128, MROWS / 128);
    dim3 gFl(128, 16);

    // ---- branch 1 ----
    ln_kernel<<<gLN, 256>>>(x1, ln11_g, ln11_b, lnA);
    ln_kernel<<<gLN, 256>>>(x2, ln12_g, ln12_b, lnB);
    tf32_gemm_kernel<<<g1k, 256, GEMM_SMEM>>>(lnA, a1_wq, q, MROWS, CDIM, CDIM, nullptr, nullptr, 0);
    tf32_gemm_kernel<<<g1k, 256, GEMM_SMEM>>>(lnB, a1_wk, k, MROWS, CDIM, CDIM, nullptr, nullptr, 0);
    tf32_gemm_kernel<<<g1k, 256, GEMM_SMEM>>>(lnB, a1_wv, v, MROWS, CDIM, CDIM, nullptr, nullptr, 0);
    flash_kernel<<<gFl, 256, FL_SMEM>>>(q, k, v, ao);
    tf32_gemm_kernel<<<g1k, 256, GEMM_SMEM>>>(ao, a1_wp, acc, MROWS, CDIM, CDIM, a1_bp, x1, 0);

    // ---- branch 2 ----
    ln_kernel<<<gLN, 256>>>(x1, ln21_g, ln21_b, lnA);
    ln_kernel<<<gLN, 256>>>(x3, ln23_g, ln23_b, lnB);
    tf32_gemm_kernel<<<g1k, 256, GEMM_SMEM>>>(lnA, a2_wq, q, MROWS, CDIM, CDIM, nullptr, nullptr, 0);
    tf32_gemm_kernel<<<g1k, 256, GEMM_SMEM>>>(lnB, a2_wk, k, MROWS, CDIM, CDIM, nullptr, nullptr, 0);
    tf32_gemm_kernel<<<g1k, 256, GEMM_SMEM>>>(lnB, a2_wv, v, MROWS, CDIM, CDIM, nullptr, nullptr, 0);
    flash_kernel<<<gFl, 256, FL_SMEM>>>(q, k, v, ao);
    tf32_gemm_kernel<<<g1k, 256, GEMM_SMEM>>>(ao, a2_wp, acc, MROWS, CDIM, CDIM, a2_bp, acc, 0);

    // ---- MLP ----
    ln_kernel<<<gLN, 256>>>(acc, ln2_g, ln2_b, lnA);
    tf32_gemm_kernel<<<gH, 256, GEMM_SMEM>>>(lnA, fc1_w, hbuf, MROWS, HID, CDIM, fc1_b, nullptr, 1);
    tf32_gemm_kernel<<<g1k, 256, GEMM_SMEM>>>(hbuf, fc2_w, out, MROWS, CDIM, HID, fc2_b, acc, 0);
}

// round 10
// speedup vs baseline: 2.1005x; 1.1122x over previous
#include <cuda_runtime.h>
#include <math.h>
#include <stdint.h>

// Problem constants
#define MROWS 8192          // B*N
#define CDIM  1024
#define HID   4096
#define NHEAD 16
#define DHEAD 64
#define SEQ   1024
#define LN_EPS 1e-5f

// ---------------- scratch (no allocations allowed) ----------------
__device__ float g_lnA[MROWS * CDIM];
__device__ float g_lnB[MROWS * CDIM];
__device__ float g_q  [MROWS * CDIM];
__device__ float g_k  [MROWS * CDIM];
__device__ float g_v  [MROWS * CDIM];
__device__ float g_ao [MROWS * CDIM];
__device__ float g_acc[MROWS * CDIM];
__device__ float g_h  [MROWS * HID];
__device__ float g_wT [16 * 1024 * 1024];   // transposed weights, 64MB

// ---------------- helpers ----------------
__device__ __forceinline__ unsigned smem_u32(const void* p) {
    unsigned r;
    asm("{ .reg .u64 t; cvta.to.shared.u64 t, %1; cvt.u32.u64 %0, t; }"
        : "=r"(r) : "l"(p));
    return r;
}
__device__ __forceinline__ float f2tf32(float x) {
    unsigned u;
    asm("cvt.rna.tf32.f32 %0, %1;" : "=r"(u) : "f"(x));
    return __uint_as_float(u);
}
__device__ __forceinline__ void cpa16(unsigned dst, const float* src) {
    asm volatile("cp.async.cg.shared.global [%0], [%1], 16;"
                 :: "r"(dst), "l"(src) : "memory");
}
// permuted feature layout within each 32-col block: pos = 4*(c&7) + ((c>>3)&3)
__device__ __forceinline__ int perm32(int c) {
    return (c & ~31) | ((c & 7) << 2) | ((c >> 3) & 3);
}
__device__ __forceinline__ void mma_tf32(float4& d,
    unsigned a0, unsigned a1, unsigned a2, unsigned a3,
    unsigned b0, unsigned b1)
{
    asm volatile(
        "mma.sync.aligned.m16n8k8.row.col.f32.tf32.tf32.f32 "
        "{%0,%1,%2,%3}, {%4,%5,%6,%7}, {%8,%9}, {%0,%1,%2,%3};\n"
        : "+f"(d.x), "+f"(d.y), "+f"(d.z), "+f"(d.w)
        : "r"(a0), "r"(a1), "r"(a2), "r"(a3), "r"(b0), "r"(b1));
}

// ---------------- LayerNorm: one block per row of 1024, permuted tf32 output ----------------
__global__ void __launch_bounds__(256) ln_kernel(
    const float* __restrict__ x, const float* __restrict__ g,
    const float* __restrict__ b, float* __restrict__ out)
{
    int row = blockIdx.x;
    int t = threadIdx.x;
    const float4* xr = (const float4*)(x + (size_t)row * CDIM);
    float4 v = xr[t];
    float s  = v.x + v.y + v.z + v.w;
    float sq = v.x * v.x + v.y * v.y + v.z * v.z + v.w * v.w;
    #pragma unroll
    for (int o = 16; o > 0; o >>= 1) {
        s  += __shfl_xor_sync(0xffffffffu, s,  o);
        sq += __shfl_xor_sync(0xffffffffu, sq, o);
    }
    __shared__ float ss[8], ssq[8];
    __shared__ float red[2];
    int w = t >> 5, lane = t & 31;
    if (lane == 0) { ss[w] = s; ssq[w] = sq; }
    __syncthreads();
    if (w == 0) {
        float a  = (lane < 8) ? ss[lane]  : 0.f;
        float aq = (lane < 8) ? ssq[lane] : 0.f;
        #pragma unroll
        for (int o = 4; o > 0; o >>= 1) {
            a  += __shfl_xor_sync(0xffffffffu, a,  o);
            aq += __shfl_xor_sync(0xffffffffu, aq, o);
        }
        if (lane == 0) {
            float mean = a * (1.0f / CDIM);
            float var  = aq * (1.0f / CDIM) - mean * mean;
            red[0] = mean;
            red[1] = rsqrtf(var + LN_EPS);
        }
    }
    __syncthreads();
    float mean = red[0], rstd = red[1];
    float4 gg = ((const float4*)g)[t];
    float4 bb = ((const float4*)b)[t];
    float o0 = f2tf32((v.x - mean) * rstd * gg.x + bb.x);
    float o1 = f2tf32((v.y - mean) * rstd * gg.y + bb.y);
    float o2 = f2tf32((v.z - mean) * rstd * gg.z + bb.z);
    float o3 = f2tf32((v.w - mean) * rstd * gg.w + bb.w);
    float* orow = out + (size_t)row * CDIM;
    int c0 = t * 4;
    orow[perm32(c0 + 0)] = o0;
    orow[perm32(c0 + 1)] = o1;
    orow[perm32(c0 + 2)] = o2;
    orow[perm32(c0 + 3)] = o3;
}

// ---------------- weight transpose: WT[n][perm(k)] = tf32(W[k][n]) ----------------
__global__ void __launch_bounds__(256) transpose_kernel(
    const float* __restrict__ W, float* __restrict__ WT, int K, int N)
{
    __shared__ float t[32][33];
    int n0 = blockIdx.x * 32, k0 = blockIdx.y * 32;
    int tx = threadIdx.x, ty = threadIdx.y;   // 32 x 8
    #pragma unroll
    for (int j = 0; j < 32; j += 8)
        t[ty + j][tx] = W[(size_t)(k0 + ty + j) * N + n0 + tx];
    __syncthreads();
    #pragma unroll
    for (int j = 0; j < 32; j += 8)
        WT[(size_t)(n0 + ty + j) * K + perm32(k0 + tx)] = f2tf32(t[tx][ty + j]);
}

// ---------------- TF32 mma.sync GEMM, cp.async 4-stage, 128x128x32 ----------------
// A[M,K] (permuted-K layout), BT[N,K] (permuted-K layout).
// SMEM per stage: A 16KB @0, B 16KB @16384. 128B rows; 16B group of row r at
// group index (g ^ ((r&1)<<2)) holds cols { g + 8ks, ks=0..3 } of that row.
#define NSTAGE 4
#define STG_BYTES 32768
#define GEMM_SMEM (NSTAGE * STG_BYTES)   // 131072

__global__ void __launch_bounds__(256, 1) tf32_gemm(
    const float* __restrict__ A, const float* __restrict__ BT, float* __restrict__ C,
    int M, int N, int K,
    const float* __restrict__ bias, const float* __restrict__ add, int act, int permC)
{
    extern __shared__ char smem[];
    unsigned sb = smem_u32(smem);
    int tid = threadIdx.x;
    int lane = tid & 31, warp = tid >> 5;
    int wm = warp & 3, wn = warp >> 2;       // wm 0..3, wn 0..1
    int g = lane >> 2, t = lane & 3;
    int bm = blockIdx.y, bn = blockIdx.x;

    float4 acc[2][8];
    #pragma unroll
    for (int i = 0; i < 2; i++)
        #pragma unroll
        for (int j = 0; j < 8; j++) acc[i][j] = make_float4(0.f, 0.f, 0.f, 0.f);

    // cp.async geometry: thread handles rows r0+32i, 16B group gc
    int r0 = tid >> 3;
    int gc = tid & 7;
    unsigned dstA0 = (unsigned)(r0 * 128 + ((gc ^ ((r0 & 1) << 2)) << 4));
    unsigned dstB0 = 16384u + dstA0;
    const float* Asrc = A  + (size_t)(bm * 128 + r0) * K + gc * 4;
    const float* Bsrc = BT + (size_t)(bn * 128 + r0) * K + gc * 4;

    // fragment load byte offsets within a stage buffer
    int swz = (g & 1) << 2;
    unsigned aL0 = (unsigned)((wm * 32 + g) * 128 + ((t ^ swz) << 4));
    unsigned aL1 = (unsigned)((wm * 32 + g) * 128 + (((t + 4) ^ swz) << 4));
    unsigned bL0 = 16384u + (unsigned)((wn * 64 + g) * 128 + ((t ^ swz) << 4));
    unsigned bL1 = 16384u + (unsigned)((wn * 64 + g) * 128 + (((t + 4) ^ swz) << 4));

    int nstg = K >> 5;

    // prologue: issue 3 stages
    #pragma unroll
    for (int p = 0; p < 3; p++) {
        unsigned db = sb + (unsigned)(p & 3) * STG_BYTES;
        const float* a = Asrc + p * 32;
        const float* bq = Bsrc + p * 32;
        #pragma unroll
        for (int i = 0; i < 4; i++) {
            cpa16(db + dstA0 + i * 4096, a  + (size_t)(32 * i) * K);
            cpa16(db + dstB0 + i * 4096, bq + (size_t)(32 * i) * K);
        }
        asm volatile("cp.async.commit_group;" ::: "memory");
    }

    for (int s = 0; s < nstg; s++) {
        asm volatile("cp.async.wait_group 2;" ::: "memory");
        __syncthreads();

        const char* sbuf = smem + (size_t)(s & 3) * STG_BYTES;

        float4 af[2][4];
        #pragma unroll
        for (int i = 0; i < 2; i++) {
            af[i][0] = *(const float4*)(sbuf + aL0 + i * 2048);
            af[i][1] = *(const float4*)(sbuf + aL0 + i * 2048 + 1024);
            af[i][2] = *(const float4*)(sbuf + aL1 + i * 2048);
            af[i][3] = *(const float4*)(sbuf + aL1 + i * 2048 + 1024);
        }

        #pragma unroll
        for (int j = 0; j < 8; j++) {
            float4 b0 = *(const float4*)(sbuf + bL0 + j * 1024);
            float4 b1 = *(const float4*)(sbuf + bL1 + j * 1024);
            const unsigned* b0u = (const unsigned*)&b0;
            const unsigned* b1u = (const unsigned*)&b1;
            #pragma unroll
            for (int ks = 0; ks < 4; ks++) {
                #pragma unroll
                for (int i = 0; i < 2; i++) {
                    const unsigned* a0u = (const unsigned*)&af[i][0];
                    const unsigned* a1u = (const unsigned*)&af[i][1];
                    const unsigned* a2u = (const unsigned*)&af[i][2];
                    const unsigned* a3u = (const unsigned*)&af[i][3];
                    mma_tf32(acc[i][j], a0u[ks], a1u[ks], a2u[ks], a3u[ks],
                             b0u[ks], b1u[ks]);
                }
            }
        }

        // refill buffer computed at iter s-1 (protected by this iter's barrier)
        if (s + 3 < nstg) {
            int p = s + 3;
            unsigned db = sb + (unsigned)(p & 3) * STG_BYTES;
            const float* a = Asrc + p * 32;
            const float* bq = Bsrc + p * 32;
            #pragma unroll
            for (int i = 0; i < 4; i++) {
                cpa16(db + dstA0 + i * 4096, a  + (size_t)(32 * i) * K);
                cpa16(db + dstB0 + i * 4096, bq + (size_t)(32 * i) * K);
            }
        }
        asm volatile("cp.async.commit_group;" ::: "memory");  // empty groups keep accounting
    }

    // epilogue
    int rbase = bm * 128 + wm * 32;
    int cbase = bn * 128 + wn * 64;
    #pragma unroll
    for (int i = 0; i < 2; i++) {
        int r0e = rbase + i * 16 + g;
        int r1e = r0e + 8;
        #pragma unroll
        for (int j = 0; j < 8; j++) {
            int c = cbase + j * 8 + t * 2;
            float v0 = acc[i][j].x, v1 = acc[i][j].y;
            float v2 = acc[i][j].z, v3 = acc[i][j].w;
            if (bias) {
                float b0 = bias[c], b1 = bias[c + 1];
                v0 += b0; v1 += b1; v2 += b0; v3 += b1;
            }
            if (act == 1) {
                v0 = 0.5f * v0 * (1.0f + erff(v0 * 0.70710678118654752f));
                v1 = 0.5f * v1 * (1.0f + erff(v1 * 0.70710678118654752f));
                v2 = 0.5f * v2 * (1.0f + erff(v2 * 0.70710678118654752f));
                v3 = 0.5f * v3 * (1.0f + erff(v3 * 0.70710678118654752f));
            }
            size_t o0 = (size_t)r0e * N;
            size_t o1 = (size_t)r1e * N;
            if (add) {
                v0 += add[o0 + c]; v1 += add[o0 + c + 1];
                v2 += add[o1 + c]; v3 += add[o1 + c + 1];
            }
            if (permC) {   // output consumed as GEMM A: permute + tf32-round
                C[o0 + perm32(c)]     = f2tf32(v0);
                C[o0 + perm32(c + 1)] = f2tf32(v1);
                C[o1 + perm32(c)]     = f2tf32(v2);
                C[o1 + perm32(c + 1)] = f2tf32(v3);
            } else {
                *(float2*)(C + o0 + c) = make_float2(v0, v1);
                *(float2*)(C + o1 + c) = make_float2(v2, v3);
            }
        }
    }
}

// ---------------- Flash attention: Br=Bc=64, d=64, fp32; permuted tf32 output ----------------
#define FL_PAD 68
#define FL_SMEM (4 * 64 * FL_PAD * 4)

__global__ void __launch_bounds__(256) flash_kernel(
    const float* __restrict__ Q, const float* __restrict__ Kx,
    const float* __restrict__ V, float* __restrict__ O)
{
    extern __shared__ float sm[];
    float (*Qts)[FL_PAD] = (float (*)[FL_PAD])(sm);
    float (*Kts)[FL_PAD] = (float (*)[FL_PAD])(sm + 64 * FL_PAD);
    float (*Vs )[FL_PAD] = (float (*)[FL_PAD])(sm + 2 * 64 * FL_PAD);
    float (*Ps )[FL_PAD] = (float (*)[FL_PAD])(sm + 3 * 64 * FL_PAD);

    int bh = blockIdx.x;
    int b = bh / NHEAD, h = bh % NHEAD;
    int qt = blockIdx.y;
    int tid = threadIdx.x;
    int tx = tid & 15, ty = tid >> 4;
    int r0 = ty * 4, c0 = tx * 4;
    size_t base = ((size_t)b * SEQ) * CDIM + h * DHEAD;

    #pragma unroll
    for (int i = 0; i < 4; i++) {
        int f = tid + i * 256;
        int row = f >> 4, c4 = f & 15;
        float4 a = *(const float4*)(Q + base + (size_t)(qt * 64 + row) * CDIM + c4 * 4);
        Qts[c4 * 4 + 0][row] = a.x;
        Qts[c4 * 4 + 1][row] = a.y;
        Qts[c4 * 4 + 2][row] = a.z;
        Qts[c4 * 4 + 3][row] = a.w;
    }

    float m[4], l[4], o[4][4];
    #pragma unroll
    for (int i = 0; i < 4; i++) {
        m[i] = -1e30f; l[i] = 0.f;
        #pragma unroll
        for (int j = 0; j < 4; j++) o[i][j] = 0.f;
    }

    const float scale = 0.125f;

    for (int kt = 0; kt < SEQ / 64; kt++) {
        __syncthreads();
        #pragma unroll
        for (int i = 0; i < 4; i++) {
            int f = tid + i * 256;
            int row = f >> 4, c4 = f & 15;
            float4 a = *(const float4*)(Kx + base + (size_t)(kt * 64 + row) * CDIM + c4 * 4);
            Kts[c4 * 4 + 0][row] = a.x;
            Kts[c4 * 4 + 1][row] = a.y;
            Kts[c4 * 4 + 2][row] = a.z;
            Kts[c4 * 4 + 3][row] = a.w;
            *(float4*)&Vs[row][c4 * 4] =
                *(const float4*)(V + base + (size_t)(kt * 64 + row) * CDIM + c4 * 4);
        }
        __syncthreads();

        float s[4][4];
        #pragma unroll
        for (int i = 0; i < 4; i++)
            #pragma unroll
            for (int j = 0; j < 4; j++) s[i][j] = 0.f;
        #pragma unroll 8
        for (int kk = 0; kk < DHEAD; kk++) {
            float4 q4 = *(float4*)&Qts[kk][r0];
            float4 k4 = *(float4*)&Kts[kk][c0];
            float qa[4] = {q4.x, q4.y, q4.z, q4.w};
            float ka[4] = {k4.x, k4.y, k4.z, k4.w};
            #pragma unroll
            for (int i = 0; i < 4; i++)
                #pragma unroll
                for (int j = 0; j < 4; j++)
                    s[i][j] += qa[i] * ka[j];
        }

        #pragma unroll
        for (int i = 0; i < 4; i++) {
            float tmax = -1e30f;
            #pragma unroll
            for (int j = 0; j < 4; j++) {
                s[i][j] *= scale;
                tmax = fmaxf(tmax, s[i][j]);
            }
            #pragma unroll
            for (int off = 8; off > 0; off >>= 1)
                tmax = fmaxf(tmax, __shfl_xor_sync(0xffffffffu, tmax, off, 16));
            float mn = fmaxf(m[i], tmax);
            float al = __expf(m[i] - mn);
            float rs = 0.f;
            #pragma unroll
            for (int j = 0; j < 4; j++) {
                s[i][j] = __expf(s[i][j] - mn);
                rs += s[i][j];
            }
            #pragma unroll
            for (int off = 8; off > 0; off >>= 1)
                rs += __shfl_xor_sync(0xffffffffu, rs, off, 16);
            l[i] = l[i] * al + rs;
            m[i] = mn;
            #pragma unroll
            for (int j = 0; j < 4; j++) o[i][j] *= al;
            *(float4*)&Ps[r0 + i][c0] = make_float4(s[i][0], s[i][1], s[i][2], s[i][3]);
        }
        __syncthreads();

        #pragma unroll 4
        for (int c = 0; c < 64; c += 4) {
            float4 p0 = *(float4*)&Ps[r0 + 0][c];
            float4 p1 = *(float4*)&Ps[r0 + 1][c];
            float4 p2 = *(float4*)&Ps[r0 + 2][c];
            float4 p3 = *(float4*)&Ps[r0 + 3][c];
            const float* pp0 = (const float*)&p0;
            const float* pp1 = (const float*)&p1;
            const float* pp2 = (const float*)&p2;
            const float* pp3 = (const float*)&p3;
            #pragma unroll
            for (int cc = 0; cc < 4; cc++) {
                float4 v4 = *(float4*)&Vs[c + cc][c0];
                float e0 = pp0[cc], e1 = pp1[cc], e2 = pp2[cc], e3 = pp3[cc];
                o[0][0] += e0 * v4.x; o[0][1] += e0 * v4.y;
                o[0][2] += e0 * v4.z; o[0][3] += e0 * v4.w;
                o[1][0] += e1 * v4.x; o[1][1] += e1 * v4.y;
                o[1][2] += e1 * v4.z; o[1][3] += e1 * v4.w;
                o[2][0] += e2 * v4.x; o[2][1] += e2 * v4.y;
                o[2][2] += e2 * v4.z; o[2][3] += e2 * v4.w;
                o[3][0] += e3 * v4.x; o[3][1] += e3 * v4.y;
                o[3][2] += e3 * v4.z; o[3][3] += e3 * v4.w;
            }
        }
    }

    // permuted + tf32-rounded output (consumed only as GEMM A)
    #pragma unroll
    for (int i = 0; i < 4; i++) {
        float inv = 1.0f / l[i];
        size_t rowo = ((size_t)b * SEQ + qt * 64 + r0 + i) * CDIM;
        int cg = h * DHEAD + c0;
        O[rowo + perm32(cg + 0)] = f2tf32(o[i][0] * inv);
        O[rowo + perm32(cg + 1)] = f2tf32(o[i][1] * inv);
        O[rowo + perm32(cg + 2)] = f2tf32(o[i][2] * inv);
        O[rowo + perm32(cg + 3)] = f2tf32(o[i][3] * inv);
    }
}

// ---------------- launch ----------------
extern "C" void kernel_launch(void* const* d_in, const int* in_sizes, int n_in,
                              void* d_out, int out_size)
{
    const float* x1     = (const float*)d_in[0];
    const float* x2     = (const float*)d_in[1];
    const float* x3     = (const float*)d_in[2];
    const float* ln11_g = (const float*)d_in[3];
    const float* ln11_b = (const float*)d_in[4];
    const float* ln12_g = (const float*)d_in[5];
    const float* ln12_b = (const float*)d_in[6];
    const float* ln21_g = (const float*)d_in[7];
    const float* ln21_b = (const float*)d_in[8];
    const float* ln23_g = (const float*)d_in[9];
    const float* ln23_b = (const float*)d_in[10];
    const float* ln2_g  = (const float*)d_in[11];
    const float* ln2_b  = (const float*)d_in[12];
    const float* a1_wq  = (const float*)d_in[13];
    const float* a1_wk  = (const float*)d_in[14];
    const float* a1_wv  = (const float*)d_in[15];
    const float* a1_wp  = (const float*)d_in[16];
    const float* a1_bp  = (const float*)d_in[17];
    const float* a2_wq  = (const float*)d_in[18];
    const float* a2_wk  = (const float*)d_in[19];
    const float* a2_wv  = (const float*)d_in[20];
    const float* a2_wp  = (const float*)d_in[21];
    const float* a2_bp  = (const float*)d_in[22];
    const float* fc1_w  = (const float*)d_in[23];
    const float* fc1_b  = (const float*)d_in[24];
    const float* fc2_w  = (const float*)d_in[25];
    const float* fc2_b  = (const float*)d_in[26];
    float* out = (float*)d_out;

    float *lnA, *lnB, *q, *k, *v, *ao, *acc, *hbuf, *wT;
    cudaGetSymbolAddress((void**)&lnA,  g_lnA);
    cudaGetSymbolAddress((void**)&lnB,  g_lnB);
    cudaGetSymbolAddress((void**)&q,    g_q);
    cudaGetSymbolAddress((void**)&k,    g_k);
    cudaGetSymbolAddress((void**)&v,    g_v);
    cudaGetSymbolAddress((void**)&ao,   g_ao);
    cudaGetSymbolAddress((void**)&acc,  g_acc);
    cudaGetSymbolAddress((void**)&hbuf, g_h);
    cudaGetSymbolAddress((void**)&wT,   g_wT);

    const size_t MB1 = 1024 * 1024;
    float* t_a1q = wT + 0 * MB1;
    float* t_a1k = wT + 1 * MB1;
    float* t_a1v = wT + 2 * MB1;
    float* t_a1p = wT + 3 * MB1;
    float* t_a2q = wT + 4 * MB1;
    float* t_a2k = wT + 5 * MB1;
    float* t_a2v = wT + 6 * MB1;
    float* t_a2p = wT + 7 * MB1;
    float* t_fc1 = wT + 8 * MB1;    // [4096, 1024]
    float* t_fc2 = wT + 12 * MB1;   // [1024, 4096]

    cudaFuncSetAttribute(flash_kernel, cudaFuncAttributeMaxDynamicSharedMemorySize, FL_SMEM);
    cudaFuncSetAttribute(tf32_gemm, cudaFuncAttributeMaxDynamicSharedMemorySize, GEMM_SMEM);

    dim3 tb(32, 8);
    dim3 gT1(CDIM / 32, CDIM / 32);
    transpose_kernel<<<gT1, tb>>>(a1_wq, t_a1q, CDIM, CDIM);
    transpose_kernel<<<gT1, tb>>>(a1_wk, t_a1k, CDIM, CDIM);
    transpose_kernel<<<gT1, tb>>>(a1_wv, t_a1v, CDIM, CDIM);
    transpose_kernel<<<gT1, tb>>>(a1_wp, t_a1p, CDIM, CDIM);
    transpose_kernel<<<gT1, tb>>>(a2_wq, t_a2q, CDIM, CDIM);
    transpose_kernel<<<gT1, tb>>>(a2_wk, t_a2k, CDIM, CDIM);
    transpose_kernel<<<gT1, tb>>>(a2_wv, t_a2v, CDIM, CDIM);
    transpose_kernel<<<gT1, tb>>>(a2_wp, t_a2p, CDIM, CDIM);
    transpose_kernel<<<dim3(HID / 32, CDIM / 32), tb>>>(fc1_w, t_fc1, CDIM, HID);
    transpose_kernel<<<dim3(CDIM / 32, HID / 32), tb>>>(fc2_w, t_fc2, HID, CDIM);

    dim3 gLN(MROWS);
    dim3 g1k(CDIM / 128, MROWS / 128);
    dim3 gH (HID  / 128, MROWS / 128);
    dim3 gFl(128, 16);

    // ---- branch 1 ----
    ln_kernel<<<gLN, 256>>>(x1, ln11_g, ln11_b, lnA);
    ln_kernel<<<gLN, 256>>>(x2, ln12_g, ln12_b, lnB);
    tf32_gemm<<<g1k, 256, GEMM_SMEM>>>(lnA, t_a1q, q, MROWS, CDIM, CDIM, nullptr, nullptr, 0, 0);
    tf32_gemm<<<g1k, 256, GEMM_SMEM>>>(lnB, t_a1k, k, MROWS, CDIM, CDIM, nullptr, nullptr, 0, 0);
    tf32_gemm<<<g1k, 256, GEMM_SMEM>>>(lnB, t_a1v, v, MROWS, CDIM, CDIM, nullptr, nullptr, 0, 0);
    flash_kernel<<<gFl, 256, FL_SMEM>>>(q, k, v, ao);
    tf32_gemm<<<g1k, 256, GEMM_SMEM>>>(ao, t_a1p, acc, MROWS, CDIM, CDIM, a1_bp, x1, 0, 0);

    // ---- branch 2 ----
    ln_kernel<<<gLN, 256>>>(x1, ln21_g, ln21_b, lnA);
    ln_kernel<<<gLN, 256>>>(x3, ln23_g, ln23_b, lnB);
    tf32_gemm<<<g1k, 256, GEMM_SMEM>>>(lnA, t_a2q, q, MROWS, CDIM, CDIM, nullptr, nullptr, 0, 0);
    tf32_gemm<<<g1k, 256, GEMM_SMEM>>>(lnB, t_a2k, k, MROWS, CDIM, CDIM, nullptr, nullptr, 0, 0);
    tf32_gemm<<<g1k, 256, GEMM_SMEM>>>(lnB, t_a2v, v, MROWS, CDIM, CDIM, nullptr, nullptr, 0, 0);
    flash_kernel<<<gFl, 256, FL_SMEM>>>(q, k, v, ao);
    tf32_gemm<<<g1k, 256, GEMM_SMEM>>>(ao, t_a2p, acc, MROWS, CDIM, CDIM, a2_bp, acc, 0, 0);

    // ---- MLP ----
    ln_kernel<<<gLN, 256>>>(acc, ln2_g, ln2_b, lnA);
    tf32_gemm<<<gH, 256, GEMM_SMEM>>>(lnA, t_fc1, hbuf, MROWS, HID, CDIM, fc1_b, nullptr, 1, 1);
    tf32_gemm<<<g1k, 256, GEMM_SMEM>>>(hbuf, t_fc2, out, MROWS, CDIM, HID, fc2_b, acc, 0, 0);
}